// round 4
// baseline (speedup 1.0000x reference)
#include <cuda_runtime.h>
#include <stdint.h>

#define N_SENS 10000
#define N_HID  400000
#define N_MOT  1000
#define E_SH   4000000
#define E_HH   16000000
#define E_HM   400000

#define SENS_WORDS 313      // ceil(10000/32)
#define HID_WORDS  12500    // 400000/32

#define GRID 296            // 148 SMs x 2 blocks (guaranteed co-resident)
#define TPB  512
#define NTHREADS (GRID * TPB)

#define G_SH (E_SH / 4)     // 1,000,000 int4-groups
#define G_HH (E_HH / 4)     // 4,000,000
#define G_HM (E_HM / 4)     // 100,000

// Scratch (__device__ globals; allocation-free rule)
__device__ uint32_t g_sens_bits[SENS_WORDS];
__device__ uint32_t g_hid_bits[HID_WORDS];
__device__ float    g_hid_in[N_HID];
__device__ float    g_hid_spk[N_HID];
__device__ float    g_mot_in[N_MOT];
// Monotonic ticket barrier counters (zero at module load; never reset —
// tickets grow across graph replays, target = (ticket/GRID+1)*GRID).
__device__ unsigned long long g_bar[4];

__device__ __forceinline__ void grid_barrier(int idx) {
    __syncthreads();
    if (threadIdx.x == 0) {
        __threadfence();
        unsigned long long ticket = atomicAdd(&g_bar[idx], 1ULL);
        unsigned long long target = (ticket / GRID + 1ULL) * GRID;
        while (*(volatile unsigned long long*)&g_bar[idx] < target) { }
        __threadfence();
    }
    __syncthreads();
}

__global__ void __launch_bounds__(TPB, 2)
snn_fused(const float* __restrict__ s_in,
          const float* __restrict__ s_mem,
          const float* __restrict__ h_mem,
          const float* __restrict__ m_mem,
          const float* __restrict__ prev_spk,
          const float4* __restrict__ w_sh,
          const float4* __restrict__ w_hh,
          const float4* __restrict__ w_hm,
          const int4* __restrict__ sh_pre,
          const int4* __restrict__ sh_post,
          const int4* __restrict__ hh_pre,
          const int4* __restrict__ hh_post,
          const int4* __restrict__ hm_pre,
          const int4* __restrict__ hm_post,
          float* __restrict__ out) {
    extern __shared__ uint32_t hb[];          // HID_WORDS words (50 KB)
    __shared__ uint32_t sb[SENS_WORDS];

    const int tid = blockIdx.x * blockDim.x + threadIdx.x;

    // ---------------- P0: zero accumulators, build spike bitmasks -----------
    // 400128 = multiple of 32 so every iterated warp is full (safe ballot)
    for (int i = tid; i < 400128; i += NTHREADS) {
        if (i < N_HID) g_hid_in[i] = 0.0f;
        if (i < N_MOT) g_mot_in[i] = 0.0f;

        int predh = (i < N_HID) ? (prev_spk[i] != 0.0f) : 0;
        uint32_t bitsh = __ballot_sync(0xFFFFFFFFu, predh);
        if ((i & 31) == 0 && (i >> 5) < HID_WORDS) g_hid_bits[i >> 5] = bitsh;

        if (i < 10016) {  // covers SENS_WORDS*32, multiple of 32
            int preds = 0;
            if (i < N_SENS) {
                float m = 0.9f * s_mem[i] + 5.0f * s_in[i];
                preds = (m > 1.0f);
            }
            uint32_t bitss = __ballot_sync(0xFFFFFFFFu, preds);
            if ((i & 31) == 0 && (i >> 5) < SENS_WORDS) g_sens_bits[i >> 5] = bitss;
        }
    }

    grid_barrier(0);

    // Stage bitmasks into shared memory (per block)
    for (int i = threadIdx.x; i < HID_WORDS; i += blockDim.x) hb[i] = g_hid_bits[i];
    for (int i = threadIdx.x; i < SENS_WORDS; i += blockDim.x) sb[i] = g_sens_bits[i];
    __syncthreads();

    // ---------------- P1a: SH edges -> g_hid_in (unroll x4 for MLP) ---------
    for (int t0 = tid; t0 < G_SH; t0 += NTHREADS * 4) {
        int4 p[4];
        bool v[4];
        #pragma unroll
        for (int k = 0; k < 4; k++) {
            int t = t0 + k * NTHREADS;
            v[k] = (t < G_SH);
            if (v[k]) p[k] = __ldcs(&sh_pre[t]);
        }
        #pragma unroll
        for (int k = 0; k < 4; k++) {
            if (!v[k]) continue;
            int t = t0 + k * NTHREADS;
            uint32_t b0 = (sb[p[k].x >> 5] >> (p[k].x & 31)) & 1u;
            uint32_t b1 = (sb[p[k].y >> 5] >> (p[k].y & 31)) & 1u;
            uint32_t b2 = (sb[p[k].z >> 5] >> (p[k].z & 31)) & 1u;
            uint32_t b3 = (sb[p[k].w >> 5] >> (p[k].w & 31)) & 1u;
            int4 q = __ldcs(&sh_post[t]);
            float4 wv = __ldcs(&w_sh[t]);
            if (b0) atomicAdd(&g_hid_in[q.x], wv.x);
            if (b1) atomicAdd(&g_hid_in[q.y], wv.y);
            if (b2) atomicAdd(&g_hid_in[q.z], wv.z);
            if (b3) atomicAdd(&g_hid_in[q.w], wv.w);
        }
    }

    // ---------------- P1b: HH edges -> g_hid_in (unroll x4, ~81% skip) ------
    for (int t0 = tid; t0 < G_HH; t0 += NTHREADS * 4) {
        int4 p[4];
        bool v[4];
        #pragma unroll
        for (int k = 0; k < 4; k++) {
            int t = t0 + k * NTHREADS;
            v[k] = (t < G_HH);
            if (v[k]) p[k] = __ldcs(&hh_pre[t]);
        }
        #pragma unroll
        for (int k = 0; k < 4; k++) {
            if (!v[k]) continue;
            int t = t0 + k * NTHREADS;
            uint32_t b0 = (hb[p[k].x >> 5] >> (p[k].x & 31)) & 1u;
            uint32_t b1 = (hb[p[k].y >> 5] >> (p[k].y & 31)) & 1u;
            uint32_t b2 = (hb[p[k].z >> 5] >> (p[k].z & 31)) & 1u;
            uint32_t b3 = (hb[p[k].w >> 5] >> (p[k].w & 31)) & 1u;
            if ((b0 | b1 | b2 | b3) == 0u) continue;
            int4 q = __ldcs(&hh_post[t]);
            float4 wv = __ldcs(&w_hh[t]);
            if (b0) atomicAdd(&g_hid_in[q.x], 0.5f * wv.x);
            if (b1) atomicAdd(&g_hid_in[q.y], 0.5f * wv.y);
            if (b2) atomicAdd(&g_hid_in[q.z], 0.5f * wv.z);
            if (b3) atomicAdd(&g_hid_in[q.w], 0.5f * wv.w);
        }
    }

    grid_barrier(1);

    // ---------------- P2: hidden LIF -> g_hid_spk ---------------------------
    {
        const float4* hm4 = (const float4*)h_mem;
        const float4* hi4 = (const float4*)g_hid_in;
        float4* hs4 = (float4*)g_hid_spk;
        for (int i = tid; i < N_HID / 4; i += NTHREADS) {
            float4 m = __ldg(&hm4[i]);
            float4 a = hi4[i];
            float4 s;
            s.x = (0.9f * m.x + 5.0f * a.x > 1.0f) ? 1.0f : 0.0f;
            s.y = (0.9f * m.y + 5.0f * a.y > 1.0f) ? 1.0f : 0.0f;
            s.z = (0.9f * m.z + 5.0f * a.z > 1.0f) ? 1.0f : 0.0f;
            s.w = (0.9f * m.w + 5.0f * a.w > 1.0f) ? 1.0f : 0.0f;
            hs4[i] = s;
        }
    }

    grid_barrier(2);

    // ---------------- P3: HM edges -> g_mot_in (unroll x2) ------------------
    for (int t0 = tid; t0 < G_HM; t0 += NTHREADS * 2) {
        int4 p[2];
        bool v[2];
        #pragma unroll
        for (int k = 0; k < 2; k++) {
            int t = t0 + k * NTHREADS;
            v[k] = (t < G_HM);
            if (v[k]) p[k] = __ldcs(&hm_pre[t]);
        }
        #pragma unroll
        for (int k = 0; k < 2; k++) {
            if (!v[k]) continue;
            int t = t0 + k * NTHREADS;
            float s0 = g_hid_spk[p[k].x];
            float s1 = g_hid_spk[p[k].y];
            float s2 = g_hid_spk[p[k].z];
            float s3 = g_hid_spk[p[k].w];
            if (s0 == 0.0f && s1 == 0.0f && s2 == 0.0f && s3 == 0.0f) continue;
            int4 q = __ldcs(&hm_post[t]);
            float4 wv = __ldcs(&w_hm[t]);
            if (s0 != 0.0f) atomicAdd(&g_mot_in[q.x], wv.x);
            if (s1 != 0.0f) atomicAdd(&g_mot_in[q.y], wv.y);
            if (s2 != 0.0f) atomicAdd(&g_mot_in[q.z], wv.z);
            if (s3 != 0.0f) atomicAdd(&g_mot_in[q.w], wv.w);
        }
    }

    grid_barrier(3);

    // ---------------- P4: motor LIF -> out ----------------------------------
    for (int i = tid; i < N_MOT; i += NTHREADS) {
        float m = 0.9f * __ldg(&m_mem[i]) + 20.0f * g_mot_in[i];
        out[i] = (m > 1.0f) ? 1.0f : 0.0f;
    }
}

extern "C" void kernel_launch(void* const* d_in, const int* in_sizes, int n_in,
                              void* d_out, int out_size) {
    const float* sensory_input     = (const float*)d_in[0];
    const float* sensory_mem       = (const float*)d_in[1];
    const float* hidden_mem        = (const float*)d_in[2];
    const float* motor_mem         = (const float*)d_in[3];
    const float* hidden_prev_spike = (const float*)d_in[4];
    const float* w_sh              = (const float*)d_in[5];
    const float* w_hh              = (const float*)d_in[6];
    const float* w_hm              = (const float*)d_in[7];
    const int*   sh_pre            = (const int*)d_in[8];
    const int*   sh_post           = (const int*)d_in[9];
    const int*   hh_pre            = (const int*)d_in[10];
    const int*   hh_post           = (const int*)d_in[11];
    const int*   hm_pre            = (const int*)d_in[12];
    const int*   hm_post           = (const int*)d_in[13];
    float* out = (float*)d_out;

    const int smem = HID_WORDS * sizeof(uint32_t);  // 50000 B dynamic
    cudaFuncSetAttribute(snn_fused, cudaFuncAttributeMaxDynamicSharedMemorySize,
                         smem);

    snn_fused<<<GRID, TPB, smem>>>(
        sensory_input, sensory_mem, hidden_mem, motor_mem, hidden_prev_spike,
        (const float4*)w_sh, (const float4*)w_hh, (const float4*)w_hm,
        (const int4*)sh_pre, (const int4*)sh_post,
        (const int4*)hh_pre, (const int4*)hh_post,
        (const int4*)hm_pre, (const int4*)hm_post,
        out);
}

// round 5
// speedup vs baseline: 1.2887x; 1.2887x over previous
#include <cuda_runtime.h>
#include <stdint.h>

#define N_SENS 10000
#define N_HID  400000
#define N_MOT  1000
#define E_SH   4000000
#define E_HH   16000000
#define E_HM   400000

#define SENS_WORDS 313      // ceil(10000/32)
#define HID_WORDS  12500    // 400000/32

// Scratch (__device__ globals; allocation-free rule)
__device__ uint32_t g_sens_bits[SENS_WORDS];
__device__ uint32_t g_hid_bits[HID_WORDS];
__device__ float    g_hid_in[N_HID];
__device__ float    g_hid_spk[N_HID];
__device__ float    g_mot_in[N_MOT];

// ---------------------------------------------------------------------------
// K1: zero accumulators, build sensory + hidden-prev spike bitmasks
// ---------------------------------------------------------------------------
__global__ void k_init(const float* __restrict__ s_in,
                       const float* __restrict__ s_mem,
                       const float* __restrict__ prev_spk) {
    int i = blockIdx.x * blockDim.x + threadIdx.x;

    if (i < N_HID) g_hid_in[i] = 0.0f;
    if (i < N_MOT) g_mot_in[i] = 0.0f;

    {   // hidden prev-spike bitmask (grid is multiple of 32 threads)
        int pred = (i < N_HID) ? (prev_spk[i] != 0.0f) : 0;
        uint32_t bits = __ballot_sync(0xFFFFFFFFu, pred);
        if ((i & 31) == 0 && (i >> 5) < HID_WORDS) g_hid_bits[i >> 5] = bits;
    }
    {   // sensory spike bitmask
        int pred = 0;
        if (i < N_SENS) {
            float m = 0.9f * s_mem[i] + 5.0f * s_in[i];
            pred = (m > 1.0f);
        }
        uint32_t bits = __ballot_sync(0xFFFFFFFFu, pred);
        if ((i & 31) == 0 && (i >> 5) < SENS_WORDS) g_sens_bits[i >> 5] = bits;
    }
}

// ---------------------------------------------------------------------------
// K2: SH edges, dense streaming (spikes ~89% live). All loads independent.
// ---------------------------------------------------------------------------
__global__ void __launch_bounds__(256, 8) k_sh(const int4* __restrict__ pre,
                                               const int4* __restrict__ post,
                                               const float4* __restrict__ w) {
    __shared__ uint32_t sb[SENS_WORDS];
    for (int i = threadIdx.x; i < SENS_WORDS; i += blockDim.x)
        sb[i] = g_sens_bits[i];
    __syncthreads();

    const int stride = gridDim.x * blockDim.x;
    for (int t = blockIdx.x * blockDim.x + threadIdx.x; t < E_SH / 4; t += stride) {
        int4 p = __ldcs(&pre[t]);     // independent loads: pre/post/w all
        int4 q = __ldcs(&post[t]);    // issue before any is consumed
        float4 wv = __ldcs(&w[t]);
        uint32_t b0 = (sb[p.x >> 5] >> (p.x & 31)) & 1u;
        uint32_t b1 = (sb[p.y >> 5] >> (p.y & 31)) & 1u;
        uint32_t b2 = (sb[p.z >> 5] >> (p.z & 31)) & 1u;
        uint32_t b3 = (sb[p.w >> 5] >> (p.w & 31)) & 1u;
        if (b0) atomicAdd(&g_hid_in[q.x], wv.x);
        if (b1) atomicAdd(&g_hid_in[q.y], wv.y);
        if (b2) atomicAdd(&g_hid_in[q.z], wv.z);
        if (b3) atomicAdd(&g_hid_in[q.w], wv.w);
    }
}

// ---------------------------------------------------------------------------
// K3: HH edges, DENSE streaming. post/w loaded unconditionally so all three
// LDG.128 are independent -> deep MLP, BW-bound. Bitmask gates atomics only.
// ---------------------------------------------------------------------------
__global__ void __launch_bounds__(512, 4) k_hh(const int4* __restrict__ pre,
                                               const int4* __restrict__ post,
                                               const float4* __restrict__ w) {
    extern __shared__ uint32_t hb[];
    for (int i = threadIdx.x; i < HID_WORDS; i += blockDim.x)
        hb[i] = g_hid_bits[i];
    __syncthreads();

    const int stride = gridDim.x * blockDim.x;
    for (int t = blockIdx.x * blockDim.x + threadIdx.x; t < E_HH / 4; t += stride) {
        int4 p = __ldcs(&pre[t]);
        int4 q = __ldcs(&post[t]);
        float4 wv = __ldcs(&w[t]);
        uint32_t b0 = (hb[p.x >> 5] >> (p.x & 31)) & 1u;
        uint32_t b1 = (hb[p.y >> 5] >> (p.y & 31)) & 1u;
        uint32_t b2 = (hb[p.z >> 5] >> (p.z & 31)) & 1u;
        uint32_t b3 = (hb[p.w >> 5] >> (p.w & 31)) & 1u;
        if (b0) atomicAdd(&g_hid_in[q.x], 0.5f * wv.x);
        if (b1) atomicAdd(&g_hid_in[q.y], 0.5f * wv.y);
        if (b2) atomicAdd(&g_hid_in[q.z], 0.5f * wv.z);
        if (b3) atomicAdd(&g_hid_in[q.w], 0.5f * wv.w);
    }
}

// ---------------------------------------------------------------------------
// K4: hidden LIF -> hid_spk (float4)
// ---------------------------------------------------------------------------
__global__ void k_hid_spike(const float4* __restrict__ h_mem) {
    int i = blockIdx.x * blockDim.x + threadIdx.x;
    if (i >= N_HID / 4) return;
    float4 m = h_mem[i];
    float4 a = reinterpret_cast<const float4*>(g_hid_in)[i];
    float4 s;
    s.x = (0.9f * m.x + 5.0f * a.x > 1.0f) ? 1.0f : 0.0f;
    s.y = (0.9f * m.y + 5.0f * a.y > 1.0f) ? 1.0f : 0.0f;
    s.z = (0.9f * m.z + 5.0f * a.z > 1.0f) ? 1.0f : 0.0f;
    s.w = (0.9f * m.w + 5.0f * a.w > 1.0f) ? 1.0f : 0.0f;
    reinterpret_cast<float4*>(g_hid_spk)[i] = s;
}

// ---------------------------------------------------------------------------
// K5: HM edges -> mot_in (dense: loads independent, spike gathers from L2)
// ---------------------------------------------------------------------------
__global__ void k_hm(const int4* __restrict__ pre,
                     const int4* __restrict__ post,
                     const float4* __restrict__ w) {
    int t = blockIdx.x * blockDim.x + threadIdx.x;
    if (t >= E_HM / 4) return;
    int4 p = __ldcs(&pre[t]);
    int4 q = __ldcs(&post[t]);
    float4 wv = __ldcs(&w[t]);
    float s0 = g_hid_spk[p.x];
    float s1 = g_hid_spk[p.y];
    float s2 = g_hid_spk[p.z];
    float s3 = g_hid_spk[p.w];
    if (s0 != 0.0f) atomicAdd(&g_mot_in[q.x], wv.x);
    if (s1 != 0.0f) atomicAdd(&g_mot_in[q.y], wv.y);
    if (s2 != 0.0f) atomicAdd(&g_mot_in[q.z], wv.z);
    if (s3 != 0.0f) atomicAdd(&g_mot_in[q.w], wv.w);
}

// ---------------------------------------------------------------------------
// K6: motor LIF -> output
// ---------------------------------------------------------------------------
__global__ void k_mot(const float* __restrict__ m_mem, float* __restrict__ out) {
    int i = blockIdx.x * blockDim.x + threadIdx.x;
    if (i >= N_MOT) return;
    float m = 0.9f * m_mem[i] + 20.0f * g_mot_in[i];
    out[i] = (m > 1.0f) ? 1.0f : 0.0f;
}

extern "C" void kernel_launch(void* const* d_in, const int* in_sizes, int n_in,
                              void* d_out, int out_size) {
    const float* sensory_input     = (const float*)d_in[0];
    const float* sensory_mem       = (const float*)d_in[1];
    const float* hidden_mem        = (const float*)d_in[2];
    const float* motor_mem         = (const float*)d_in[3];
    const float* hidden_prev_spike = (const float*)d_in[4];
    const float* w_sh              = (const float*)d_in[5];
    const float* w_hh              = (const float*)d_in[6];
    const float* w_hm              = (const float*)d_in[7];
    const int*   sh_pre            = (const int*)d_in[8];
    const int*   sh_post           = (const int*)d_in[9];
    const int*   hh_pre            = (const int*)d_in[10];
    const int*   hh_post           = (const int*)d_in[11];
    const int*   hm_pre            = (const int*)d_in[12];
    const int*   hm_post           = (const int*)d_in[13];
    float* out = (float*)d_out;

    static bool attr_set = false;
    const int hh_smem = HID_WORDS * sizeof(uint32_t);  // 50000 bytes
    if (!attr_set) {
        cudaFuncSetAttribute(k_hh, cudaFuncAttributeMaxDynamicSharedMemorySize,
                             hh_smem);
        attr_set = true;
    }

    k_init<<<(N_HID + 255) / 256, 256>>>(sensory_input, sensory_mem,
                                         hidden_prev_spike);

    // SH: 2048 threads/SM, grid-stride
    k_sh<<<148 * 8, 256>>>((const int4*)sh_pre, (const int4*)sh_post,
                           (const float4*)w_sh);

    // HH: 4 blocks/SM x 512 threads (200 KB smem/SM), dense streaming
    k_hh<<<148 * 4, 512, hh_smem>>>((const int4*)hh_pre, (const int4*)hh_post,
                                    (const float4*)w_hh);

    k_hid_spike<<<(N_HID / 4 + 255) / 256, 256>>>((const float4*)hidden_mem);

    k_hm<<<(E_HM / 4 + 255) / 256, 256>>>((const int4*)hm_pre,
                                          (const int4*)hm_post,
                                          (const float4*)w_hm);

    k_mot<<<(N_MOT + 255) / 256, 256>>>(motor_mem, out);
}

// round 6
// speedup vs baseline: 1.2947x; 1.0047x over previous
#include <cuda_runtime.h>
#include <stdint.h>

#define N_SENS 10000
#define N_HID  400000
#define N_MOT  1000
#define E_SH   4000000
#define E_HH   16000000
#define E_HM   400000

#define SENS_WORDS 313      // ceil(10000/32)
#define HID_WORDS  12500    // 400000/32

// Scratch (__device__ globals; allocation-free rule)
__device__ uint32_t g_sens_bits[SENS_WORDS];
__device__ uint32_t g_hid_bits[HID_WORDS];
__device__ float    g_hid_in[N_HID];
__device__ float    g_hid_spk[N_HID];
__device__ float    g_mot_in[N_MOT];
// Monotonic ticket barrier (never reset; grows across graph replays)
__device__ unsigned long long g_tbar[2];

// ---------------------------------------------------------------------------
// K1: zero accumulators, build sensory + hidden-prev spike bitmasks
// ---------------------------------------------------------------------------
__global__ void k_init(const float* __restrict__ s_in,
                       const float* __restrict__ s_mem,
                       const float* __restrict__ prev_spk) {
    int i = blockIdx.x * blockDim.x + threadIdx.x;

    if (i < N_HID) g_hid_in[i] = 0.0f;
    if (i < N_MOT) g_mot_in[i] = 0.0f;

    {   // hidden prev-spike bitmask (grid is multiple of 32 threads)
        int pred = (i < N_HID) ? (prev_spk[i] != 0.0f) : 0;
        uint32_t bits = __ballot_sync(0xFFFFFFFFu, pred);
        if ((i & 31) == 0 && (i >> 5) < HID_WORDS) g_hid_bits[i >> 5] = bits;
    }
    {   // sensory spike bitmask
        int pred = 0;
        if (i < N_SENS) {
            float m = 0.9f * s_mem[i] + 5.0f * s_in[i];
            pred = (m > 1.0f);
        }
        uint32_t bits = __ballot_sync(0xFFFFFFFFu, pred);
        if ((i & 31) == 0 && (i >> 5) < SENS_WORDS) g_sens_bits[i >> 5] = bits;
    }
}

// ---------------------------------------------------------------------------
// K2: SH edges, dense streaming (spikes ~89% live). All loads independent.
// ---------------------------------------------------------------------------
__global__ void __launch_bounds__(256, 8) k_sh(const int4* __restrict__ pre,
                                               const int4* __restrict__ post,
                                               const float4* __restrict__ w) {
    __shared__ uint32_t sb[SENS_WORDS];
    for (int i = threadIdx.x; i < SENS_WORDS; i += blockDim.x)
        sb[i] = g_sens_bits[i];
    __syncthreads();

    const int stride = gridDim.x * blockDim.x;
    for (int t = blockIdx.x * blockDim.x + threadIdx.x; t < E_SH / 4; t += stride) {
        int4 p = __ldcs(&pre[t]);
        int4 q = __ldcs(&post[t]);
        float4 wv = __ldcs(&w[t]);
        uint32_t b0 = (sb[p.x >> 5] >> (p.x & 31)) & 1u;
        uint32_t b1 = (sb[p.y >> 5] >> (p.y & 31)) & 1u;
        uint32_t b2 = (sb[p.z >> 5] >> (p.z & 31)) & 1u;
        uint32_t b3 = (sb[p.w >> 5] >> (p.w & 31)) & 1u;
        if (b0) atomicAdd(&g_hid_in[q.x], wv.x);
        if (b1) atomicAdd(&g_hid_in[q.y], wv.y);
        if (b2) atomicAdd(&g_hid_in[q.z], wv.z);
        if (b3) atomicAdd(&g_hid_in[q.w], wv.w);
    }
}

// ---------------------------------------------------------------------------
// K3: HH edges, dense streaming. Three independent LDG.128 -> deep MLP.
// ---------------------------------------------------------------------------
__global__ void __launch_bounds__(512, 4) k_hh(const int4* __restrict__ pre,
                                               const int4* __restrict__ post,
                                               const float4* __restrict__ w) {
    extern __shared__ uint32_t hb[];
    for (int i = threadIdx.x; i < HID_WORDS; i += blockDim.x)
        hb[i] = g_hid_bits[i];
    __syncthreads();

    const int stride = gridDim.x * blockDim.x;
    for (int t = blockIdx.x * blockDim.x + threadIdx.x; t < E_HH / 4; t += stride) {
        int4 p = __ldcs(&pre[t]);
        int4 q = __ldcs(&post[t]);
        float4 wv = __ldcs(&w[t]);
        uint32_t b0 = (hb[p.x >> 5] >> (p.x & 31)) & 1u;
        uint32_t b1 = (hb[p.y >> 5] >> (p.y & 31)) & 1u;
        uint32_t b2 = (hb[p.z >> 5] >> (p.z & 31)) & 1u;
        uint32_t b3 = (hb[p.w >> 5] >> (p.w & 31)) & 1u;
        if (b0) atomicAdd(&g_hid_in[q.x], 0.5f * wv.x);
        if (b1) atomicAdd(&g_hid_in[q.y], 0.5f * wv.y);
        if (b2) atomicAdd(&g_hid_in[q.z], 0.5f * wv.z);
        if (b3) atomicAdd(&g_hid_in[q.w], 0.5f * wv.w);
    }
}

// ---------------------------------------------------------------------------
// K4 (fused tail): hidden LIF -> hid_spk ; barrier ; HM edges ; barrier ; motor
// 148 blocks x 512 threads, guaranteed co-resident (1 block/SM).
// ---------------------------------------------------------------------------
#define TGRID 148
#define TTPB  512
#define TN    (TGRID * TTPB)

__device__ __forceinline__ void tail_barrier(int idx) {
    __syncthreads();
    if (threadIdx.x == 0) {
        __threadfence();
        unsigned long long ticket = atomicAdd(&g_tbar[idx], 1ULL);
        unsigned long long target = (ticket / TGRID + 1ULL) * TGRID;
        while (*(volatile unsigned long long*)&g_tbar[idx] < target) { }
        __threadfence();
    }
    __syncthreads();
}

__global__ void __launch_bounds__(TTPB, 1)
k_tail(const float4* __restrict__ h_mem,
       const float* __restrict__ m_mem,
       const int4* __restrict__ hm_pre,
       const int4* __restrict__ hm_post,
       const float4* __restrict__ hm_w,
       float* __restrict__ out) {
    const int tid = blockIdx.x * blockDim.x + threadIdx.x;

    // hidden LIF
    {
        const float4* hi4 = (const float4*)g_hid_in;
        float4* hs4 = (float4*)g_hid_spk;
        for (int i = tid; i < N_HID / 4; i += TN) {
            float4 m = __ldg(&h_mem[i]);
            float4 a = hi4[i];
            float4 s;
            s.x = (0.9f * m.x + 5.0f * a.x > 1.0f) ? 1.0f : 0.0f;
            s.y = (0.9f * m.y + 5.0f * a.y > 1.0f) ? 1.0f : 0.0f;
            s.z = (0.9f * m.z + 5.0f * a.z > 1.0f) ? 1.0f : 0.0f;
            s.w = (0.9f * m.w + 5.0f * a.w > 1.0f) ? 1.0f : 0.0f;
            hs4[i] = s;
        }
    }

    tail_barrier(0);

    // HM edges (dense independent loads; spike gather hits L2)
    for (int t = tid; t < E_HM / 4; t += TN) {
        int4 p = __ldcs(&hm_pre[t]);
        int4 q = __ldcs(&hm_post[t]);
        float4 wv = __ldcs(&hm_w[t]);
        float s0 = g_hid_spk[p.x];
        float s1 = g_hid_spk[p.y];
        float s2 = g_hid_spk[p.z];
        float s3 = g_hid_spk[p.w];
        if (s0 != 0.0f) atomicAdd(&g_mot_in[q.x], wv.x);
        if (s1 != 0.0f) atomicAdd(&g_mot_in[q.y], wv.y);
        if (s2 != 0.0f) atomicAdd(&g_mot_in[q.z], wv.z);
        if (s3 != 0.0f) atomicAdd(&g_mot_in[q.w], wv.w);
    }

    tail_barrier(1);

    // motor LIF
    for (int i = tid; i < N_MOT; i += TN) {
        float m = 0.9f * __ldg(&m_mem[i]) + 20.0f * g_mot_in[i];
        out[i] = (m > 1.0f) ? 1.0f : 0.0f;
    }
}

extern "C" void kernel_launch(void* const* d_in, const int* in_sizes, int n_in,
                              void* d_out, int out_size) {
    const float* sensory_input     = (const float*)d_in[0];
    const float* sensory_mem       = (const float*)d_in[1];
    const float* hidden_mem        = (const float*)d_in[2];
    const float* motor_mem         = (const float*)d_in[3];
    const float* hidden_prev_spike = (const float*)d_in[4];
    const float* w_sh              = (const float*)d_in[5];
    const float* w_hh              = (const float*)d_in[6];
    const float* w_hm              = (const float*)d_in[7];
    const int*   sh_pre            = (const int*)d_in[8];
    const int*   sh_post           = (const int*)d_in[9];
    const int*   hh_pre            = (const int*)d_in[10];
    const int*   hh_post           = (const int*)d_in[11];
    const int*   hm_pre            = (const int*)d_in[12];
    const int*   hm_post           = (const int*)d_in[13];
    float* out = (float*)d_out;

    static bool once = false;
    static cudaStream_t s1;
    static cudaEvent_t ev_fork, ev_join;
    const int hh_smem = HID_WORDS * sizeof(uint32_t);  // 50000 bytes
    if (!once) {
        cudaFuncSetAttribute(k_hh, cudaFuncAttributeMaxDynamicSharedMemorySize,
                             hh_smem);
        cudaStreamCreateWithFlags(&s1, cudaStreamNonBlocking);
        cudaEventCreateWithFlags(&ev_fork, cudaEventDisableTiming);
        cudaEventCreateWithFlags(&ev_join, cudaEventDisableTiming);
        once = true;
    }

    // init on the main (captured) stream
    k_init<<<(N_HID + 255) / 256, 256>>>(sensory_input, sensory_mem,
                                         hidden_prev_spike);

    // fork: SH runs on side stream concurrently with HH on main stream
    cudaEventRecord(ev_fork, 0);
    cudaStreamWaitEvent(s1, ev_fork, 0);

    k_sh<<<148 * 8, 256, 0, s1>>>((const int4*)sh_pre, (const int4*)sh_post,
                                  (const float4*)w_sh);

    k_hh<<<148 * 4, 512, hh_smem>>>((const int4*)hh_pre, (const int4*)hh_post,
                                    (const float4*)w_hh);

    // join: main stream waits for SH before the tail reads g_hid_in
    cudaEventRecord(ev_join, s1);
    cudaStreamWaitEvent(0, ev_join, 0);

    k_tail<<<TGRID, TTPB>>>((const float4*)hidden_mem, motor_mem,
                            (const int4*)hm_pre, (const int4*)hm_post,
                            (const float4*)w_hm, out);
}

// round 7
// speedup vs baseline: 1.3260x; 1.0242x over previous
#include <cuda_runtime.h>
#include <stdint.h>

#define N_SENS 10000
#define N_HID  400000
#define N_MOT  1000
#define E_SH   4000000
#define E_HH   16000000
#define E_HM   400000

#define SENS_WORDS 313      // ceil(10000/32)
#define HID_WORDS  12500    // 400000/32

// Scratch (__device__ globals; allocation-free rule)
__device__ uint32_t g_sens_bits[SENS_WORDS];
__device__ uint32_t g_hid_bits[HID_WORDS];
__device__ float    g_hid_in[N_HID];
__device__ float    g_hid_spk[N_HID];
__device__ float    g_mot_in[N_MOT];

// ---------------------------------------------------------------------------
// K1: zero accumulators, build sensory + hidden-prev spike bitmasks
// ---------------------------------------------------------------------------
__global__ void k_init(const float* __restrict__ s_in,
                       const float* __restrict__ s_mem,
                       const float* __restrict__ prev_spk) {
    int i = blockIdx.x * blockDim.x + threadIdx.x;

    if (i < N_HID) g_hid_in[i] = 0.0f;
    if (i < N_MOT) g_mot_in[i] = 0.0f;

    {   // hidden prev-spike bitmask (grid is multiple of 32 threads)
        int pred = (i < N_HID) ? (prev_spk[i] != 0.0f) : 0;
        uint32_t bits = __ballot_sync(0xFFFFFFFFu, pred);
        if ((i & 31) == 0 && (i >> 5) < HID_WORDS) g_hid_bits[i >> 5] = bits;
    }
    {   // sensory spike bitmask
        int pred = 0;
        if (i < N_SENS) {
            float m = 0.9f * s_mem[i] + 5.0f * s_in[i];
            pred = (m > 1.0f);
        }
        uint32_t bits = __ballot_sync(0xFFFFFFFFu, pred);
        if ((i & 31) == 0 && (i >> 5) < SENS_WORDS) g_sens_bits[i >> 5] = bits;
    }
}

// ---------------------------------------------------------------------------
// K2: SH edges, dense streaming (spikes ~89% live). All loads independent.
// ---------------------------------------------------------------------------
__global__ void __launch_bounds__(256, 8) k_sh(const int4* __restrict__ pre,
                                               const int4* __restrict__ post,
                                               const float4* __restrict__ w) {
    __shared__ uint32_t sb[SENS_WORDS];
    for (int i = threadIdx.x; i < SENS_WORDS; i += blockDim.x)
        sb[i] = g_sens_bits[i];
    __syncthreads();

    const int stride = gridDim.x * blockDim.x;
    for (int t = blockIdx.x * blockDim.x + threadIdx.x; t < E_SH / 4; t += stride) {
        int4 p = __ldcs(&pre[t]);
        int4 q = __ldcs(&post[t]);
        float4 wv = __ldcs(&w[t]);
        uint32_t b0 = (sb[p.x >> 5] >> (p.x & 31)) & 1u;
        uint32_t b1 = (sb[p.y >> 5] >> (p.y & 31)) & 1u;
        uint32_t b2 = (sb[p.z >> 5] >> (p.z & 31)) & 1u;
        uint32_t b3 = (sb[p.w >> 5] >> (p.w & 31)) & 1u;
        if (b0) atomicAdd(&g_hid_in[q.x], wv.x);
        if (b1) atomicAdd(&g_hid_in[q.y], wv.y);
        if (b2) atomicAdd(&g_hid_in[q.z], wv.z);
        if (b3) atomicAdd(&g_hid_in[q.w], wv.w);
    }
}

// ---------------------------------------------------------------------------
// K3: HH edges, dense streaming. Three independent LDG.128 -> deep MLP.
// ---------------------------------------------------------------------------
__global__ void __launch_bounds__(512, 4) k_hh(const int4* __restrict__ pre,
                                               const int4* __restrict__ post,
                                               const float4* __restrict__ w) {
    extern __shared__ uint32_t hb[];
    for (int i = threadIdx.x; i < HID_WORDS; i += blockDim.x)
        hb[i] = g_hid_bits[i];
    __syncthreads();

    const int stride = gridDim.x * blockDim.x;
    for (int t = blockIdx.x * blockDim.x + threadIdx.x; t < E_HH / 4; t += stride) {
        int4 p = __ldcs(&pre[t]);
        int4 q = __ldcs(&post[t]);
        float4 wv = __ldcs(&w[t]);
        uint32_t b0 = (hb[p.x >> 5] >> (p.x & 31)) & 1u;
        uint32_t b1 = (hb[p.y >> 5] >> (p.y & 31)) & 1u;
        uint32_t b2 = (hb[p.z >> 5] >> (p.z & 31)) & 1u;
        uint32_t b3 = (hb[p.w >> 5] >> (p.w & 31)) & 1u;
        if (b0) atomicAdd(&g_hid_in[q.x], 0.5f * wv.x);
        if (b1) atomicAdd(&g_hid_in[q.y], 0.5f * wv.y);
        if (b2) atomicAdd(&g_hid_in[q.z], 0.5f * wv.z);
        if (b3) atomicAdd(&g_hid_in[q.w], 0.5f * wv.w);
    }
}

// ---------------------------------------------------------------------------
// K4: hidden LIF -> hid_spk (float4)
// ---------------------------------------------------------------------------
__global__ void k_hid_spike(const float4* __restrict__ h_mem) {
    int i = blockIdx.x * blockDim.x + threadIdx.x;
    if (i >= N_HID / 4) return;
    float4 m = h_mem[i];
    float4 a = reinterpret_cast<const float4*>(g_hid_in)[i];
    float4 s;
    s.x = (0.9f * m.x + 5.0f * a.x > 1.0f) ? 1.0f : 0.0f;
    s.y = (0.9f * m.y + 5.0f * a.y > 1.0f) ? 1.0f : 0.0f;
    s.z = (0.9f * m.z + 5.0f * a.z > 1.0f) ? 1.0f : 0.0f;
    s.w = (0.9f * m.w + 5.0f * a.w > 1.0f) ? 1.0f : 0.0f;
    reinterpret_cast<float4*>(g_hid_spk)[i] = s;
}

// ---------------------------------------------------------------------------
// K5: HM edges -> mot_in (dense independent loads)
// ---------------------------------------------------------------------------
__global__ void k_hm(const int4* __restrict__ pre,
                     const int4* __restrict__ post,
                     const float4* __restrict__ w) {
    int t = blockIdx.x * blockDim.x + threadIdx.x;
    if (t >= E_HM / 4) return;
    int4 p = __ldcs(&pre[t]);
    int4 q = __ldcs(&post[t]);
    float4 wv = __ldcs(&w[t]);
    float s0 = g_hid_spk[p.x];
    float s1 = g_hid_spk[p.y];
    float s2 = g_hid_spk[p.z];
    float s3 = g_hid_spk[p.w];
    if (s0 != 0.0f) atomicAdd(&g_mot_in[q.x], wv.x);
    if (s1 != 0.0f) atomicAdd(&g_mot_in[q.y], wv.y);
    if (s2 != 0.0f) atomicAdd(&g_mot_in[q.z], wv.z);
    if (s3 != 0.0f) atomicAdd(&g_mot_in[q.w], wv.w);
}

// ---------------------------------------------------------------------------
// K6: motor LIF -> output
// ---------------------------------------------------------------------------
__global__ void k_mot(const float* __restrict__ m_mem, float* __restrict__ out) {
    int i = blockIdx.x * blockDim.x + threadIdx.x;
    if (i >= N_MOT) return;
    float m = 0.9f * m_mem[i] + 20.0f * g_mot_in[i];
    out[i] = (m > 1.0f) ? 1.0f : 0.0f;
}

extern "C" void kernel_launch(void* const* d_in, const int* in_sizes, int n_in,
                              void* d_out, int out_size) {
    const float* sensory_input     = (const float*)d_in[0];
    const float* sensory_mem       = (const float*)d_in[1];
    const float* hidden_mem        = (const float*)d_in[2];
    const float* motor_mem         = (const float*)d_in[3];
    const float* hidden_prev_spike = (const float*)d_in[4];
    const float* w_sh              = (const float*)d_in[5];
    const float* w_hh              = (const float*)d_in[6];
    const float* w_hm              = (const float*)d_in[7];
    const int*   sh_pre            = (const int*)d_in[8];
    const int*   sh_post           = (const int*)d_in[9];
    const int*   hh_pre            = (const int*)d_in[10];
    const int*   hh_post           = (const int*)d_in[11];
    const int*   hm_pre            = (const int*)d_in[12];
    const int*   hm_post           = (const int*)d_in[13];
    float* out = (float*)d_out;

    static bool once = false;
    static cudaStream_t s1;
    static cudaEvent_t ev_fork, ev_join;
    const int hh_smem = HID_WORDS * sizeof(uint32_t);  // 50000 bytes
    if (!once) {
        cudaFuncSetAttribute(k_hh, cudaFuncAttributeMaxDynamicSharedMemorySize,
                             hh_smem);
        cudaStreamCreateWithFlags(&s1, cudaStreamNonBlocking);
        cudaEventCreateWithFlags(&ev_fork, cudaEventDisableTiming);
        cudaEventCreateWithFlags(&ev_join, cudaEventDisableTiming);
        once = true;
    }

    // init on the main (captured) stream
    k_init<<<(N_HID + 255) / 256, 256>>>(sensory_input, sensory_mem,
                                         hidden_prev_spike);

    // fork: SH runs on side stream concurrently with HH on main stream
    cudaEventRecord(ev_fork, 0);
    cudaStreamWaitEvent(s1, ev_fork, 0);

    k_sh<<<148 * 8, 256, 0, s1>>>((const int4*)sh_pre, (const int4*)sh_post,
                                  (const float4*)w_sh);

    k_hh<<<148 * 4, 512, hh_smem>>>((const int4*)hh_pre, (const int4*)hh_post,
                                    (const float4*)w_hh);

    // join: main stream waits for SH before reading g_hid_in
    cudaEventRecord(ev_join, s1);
    cudaStreamWaitEvent(0, ev_join, 0);

    k_hid_spike<<<(N_HID / 4 + 255) / 256, 256>>>((const float4*)hidden_mem);

    k_hm<<<(E_HM / 4 + 255) / 256, 256>>>((const int4*)hm_pre,
                                          (const int4*)hm_post,
                                          (const float4*)w_hm);

    k_mot<<<(N_MOT + 255) / 256, 256>>>(motor_mem, out);
}